// round 14
// baseline (speedup 1.0000x reference)
#include <cuda_runtime.h>
#include <cuda_bf16.h>
#include <math.h>
#include <stdint.h>

#define SS 512
#define BB 256
#define EE 256
#define HH 256
#define GG 1024   // 4*H
#define TT 32

// Scratch (device globals: allocation-free contract)
__device__ float g_gx[2][SS][BB][GG];        // pre-activations
__device__ float g_h[2][SS + 1][BB][HH];     // fp32 hidden states (for emit)
__device__ float g_emit[BB][SS][TT];         // emission scores

// ---------------------------------------------------------------------------
__device__ __forceinline__ void mma_bf16(float d[4], const uint32_t a[4], const uint32_t b[2]) {
    asm volatile(
        "mma.sync.aligned.m16n8k16.row.col.f32.bf16.bf16.f32 "
        "{%0,%1,%2,%3}, {%4,%5,%6,%7}, {%8,%9}, {%0,%1,%2,%3};\n"
        : "+f"(d[0]), "+f"(d[1]), "+f"(d[2]), "+f"(d[3])
        : "r"(a[0]), "r"(a[1]), "r"(a[2]), "r"(a[3]), "r"(b[0]), "r"(b[1]));
}

__device__ __forceinline__ void ldsm_x4(uint32_t r[4], uint32_t addr) {
    asm volatile("ldmatrix.sync.aligned.m8n8.x4.shared.b16 {%0,%1,%2,%3}, [%4];"
        : "=r"(r[0]), "=r"(r[1]), "=r"(r[2]), "=r"(r[3]) : "r"(addr));
}

__device__ __forceinline__ uint32_t pack_bf16(float lo, float hi) {
    __nv_bfloat162 t = __floats2bfloat162_rn(lo, hi);
    return *(uint32_t*)&t;
}

__device__ __forceinline__ uint32_t smem_u32(const void* p) {
    uint32_t a;
    asm("{ .reg .u64 t; cvta.to.shared.u64 t, %1; cvt.u32.u64 %0, t; }"
        : "=r"(a) : "l"(p));
    return a;
}

__device__ __forceinline__ float tanh_fast(float x) {
    float y;
    asm("tanh.approx.f32 %0, %1;" : "=f"(y) : "f"(x));
    return y;
}
__device__ __forceinline__ float sigmoid_fast(float x) {
    return fmaf(tanh_fast(0.5f * x), 0.5f, 0.5f);
}

#define CLUSTER_SYNC() do { \
    asm volatile("barrier.cluster.arrive.aligned;" ::: "memory"); \
    asm volatile("barrier.cluster.wait.aligned;" ::: "memory"); \
} while (0)

// ---------------------------------------------------------------------------
// Input projection with fused embedding gather (bf16 MMA + ldmatrix):
//   gx[dir][s][b][n] = sum_e embed[row][e] * W_ih[n][e] + b_ih[n] + b_hh[n]
// Block tile: 64 (batch rows at one s) x 128 (gate cols), K=256 smem-resident.
// (R8-exact)
// ---------------------------------------------------------------------------
#define INP_SMEM ((64 + 128) * 132 * 4)

__global__ __launch_bounds__(256) void gemm_inproj_tc(
    const float* __restrict__ embed,
    const float* __restrict__ Wf, const float* __restrict__ Wb,
    const float* __restrict__ bih_f, const float* __restrict__ bhh_f,
    const float* __restrict__ bih_b, const float* __restrict__ bhh_b,
    const int* __restrict__ sent, const int* __restrict__ lens)
{
    extern __shared__ uint32_t smw[];
    uint32_t* au = smw;              // A: 64 rows x 132 words (bf16x2)
    uint32_t* wu = smw + 64 * 132;   // W: 128 cols x 132 words
    __shared__ int rowid[64];

    const int dir = blockIdx.z;
    const int m0 = blockIdx.x * 64;
    const int n0 = blockIdx.y * 128;
    const int s  = m0 >> 8;
    const int bf = m0 & 255;
    if (s >= lens[bf]) return;   // lengths sorted desc

    const int tid = threadIdx.x;
    if (tid < 64) {
        int b = bf + tid;
        int len = lens[b];
        int ss = (dir == 1 && s < len) ? (len - 1 - s) : s;
        rowid[tid] = sent[b * SS + ss];
    }
    __syncthreads();

    for (int idx = tid; idx < 64 * 64; idx += 256) {
        int r = idx >> 6, q4 = idx & 63;
        float4 v = *(const float4*)(embed + (size_t)rowid[r] * EE + q4 * 4);
        au[r * 132 + q4 * 2]     = pack_bf16(v.x, v.y);
        au[r * 132 + q4 * 2 + 1] = pack_bf16(v.z, v.w);
    }
    const float* __restrict__ W = dir ? Wb : Wf;
    for (int idx = tid; idx < 128 * 64; idx += 256) {
        int c = idx >> 6, q4 = idx & 63;
        float4 w = *(const float4*)(W + (size_t)(n0 + c) * EE + q4 * 4);
        wu[c * 132 + q4 * 2]     = pack_bf16(w.x, w.y);
        wu[c * 132 + q4 * 2 + 1] = pack_bf16(w.z, w.w);
    }
    __syncthreads();

    const int lane = tid & 31, wid = tid >> 5;
    const int wm = wid & 3, wn = wid >> 2;
    const int lr = lane >> 2, lc = lane & 3;

    float acc[8][4];
    #pragma unroll
    for (int i = 0; i < 8; i++)
        #pragma unroll
        for (int j = 0; j < 4; j++) acc[i][j] = 0.f;

    const uint32_t au_addr = smem_u32(au);
    const uint32_t wu_addr = smem_u32(wu);
    const uint32_t a_base = au_addr +
        (((wm * 16 + (lane & 15)) * 132 + ((lane >> 4) << 2)) << 2);
    const uint32_t b_base = wu_addr +
        ((((wn * 64) + (lane & 7) + ((lane >> 4) << 3)) * 132 + (((lane >> 3) & 1) << 2)) << 2);

    #pragma unroll 4
    for (int t = 0; t < 16; t++) {        // k = t*16
        uint32_t a[4];
        ldsm_x4(a, a_base + t * 32);
        #pragma unroll
        for (int p = 0; p < 4; p++) {
            uint32_t bb[4];
            ldsm_x4(bb, b_base + p * (16 * 132 * 4) + t * 32);
            mma_bf16(acc[p * 2],     a, bb);
            mma_bf16(acc[p * 2 + 1], a, bb + 2);
        }
    }

    const float* bi = dir ? bih_b : bih_f;
    const float* bh = dir ? bhh_b : bhh_f;
    float* gxp = &g_gx[dir][0][0][0];
    const int row = m0 + wm * 16 + lr;
    #pragma unroll
    for (int nf = 0; nf < 8; nf++) {
        int n = n0 + wn * 64 + nf * 8 + lc * 2;
        float b0v = bi[n] + bh[n];
        float b1v = bi[n + 1] + bh[n + 1];
        *(float2*)(gxp + (size_t)row * GG + n) =
            make_float2(acc[nf][0] + b0v, acc[nf][1] + b1v);
        *(float2*)(gxp + (size_t)(row + 8) * GG + n) =
            make_float2(acc[nf][2] + b0v, acc[nf][3] + b1v);
    }
}

// ---------------------------------------------------------------------------
// Persistent bidirectional LSTM (R8-exact): clusters of 8 CTAs per
// (dir, 16-batch tile), 256 CTAs -> 2 clusters/SM.
// ---------------------------------------------------------------------------
#define LSTM_ST_WORDS (16 * 132)           // fp32 staging [16][132]
#define LSTM_WS_WORDS (128 * 132)          // bf16x2 weights [128 cols][132]
#define LSTM_HS_WORDS (2 * 16 * 132)       // bf16x2 h, double-buffered
#define LSTM_SMEM ((LSTM_ST_WORDS + LSTM_WS_WORDS + LSTM_HS_WORDS) * 4)

__global__ __launch_bounds__(256, 2) __cluster_dims__(8, 1, 1)
void lstm_persist(
    const float* __restrict__ Whh_f, const float* __restrict__ Whh_b,
    const int* __restrict__ lens)
{
    extern __shared__ float smf[];
    float* st = smf;                                    // [16][132] fp32
    uint32_t* wsu = (uint32_t*)(smf + LSTM_ST_WORDS);   // [128][132] bf16x2
    uint32_t* hsu = wsu + LSTM_WS_WORDS;                // [2][16][132] bf16x2

    const int tid = threadIdx.x;
    const int jt  = blockIdx.x;          // cluster rank 0..7 -> j-cols jt*32..
    const int dir = blockIdx.y >> 4;
    const int mb  = blockIdx.y & 15;
    const int b0  = mb * 16;
    const int lenmax = lens[b0];         // same for whole cluster

    // Load bf16 weights. Local col c (0..127): gate g=c>>5, j=jt*32+(c&31)
    const float* __restrict__ W = dir ? Whh_b : Whh_f;
    for (int idx = tid; idx < 128 * 64; idx += 256) {
        int c = idx >> 6, q4 = idx & 63;
        int n = ((c >> 5) << 8) + jt * 32 + (c & 31);
        float4 w = *(const float4*)(W + (size_t)n * HH + q4 * 4);
        wsu[c * 132 + q4 * 2]     = pack_bf16(w.x, w.y);
        wsu[c * 132 + q4 * 2 + 1] = pack_bf16(w.z, w.w);
    }
    for (int idx = tid; idx < LSTM_HS_WORDS; idx += 256) hsu[idx] = 0u;

    const int lane = tid & 31, w = tid >> 5;
    const int lr = lane >> 2, lc = lane & 3;
    const int bl  = tid >> 4;            // epilogue batch row 0..15
    const int jl2 = (tid & 15) * 2;      // epilogue j pair

    float creg[2] = {0.f, 0.f};

    const float* gxbase = &g_gx[dir][0][0][0];
    float* hbase = &g_h[dir][0][0][0];
    const uint32_t hs_addr = smem_u32(hsu);
    const uint32_t ws_addr = smem_u32(wsu);
    const uint32_t a_base = hs_addr +
        ((((lane & 15)) * 132 + ((lane >> 4) << 2)) << 2);
    const uint32_t b_base = ws_addr +
        ((((w * 16) + (lane & 7) + ((lane >> 4) << 3)) * 132 + (((lane >> 3) & 1) << 2)) << 2);

    __syncthreads();     // weights + zeroed h ready
    // peers must see our zeroed h buffers before their step-0 remote writes
    CLUSTER_SYNC();

    for (int s = 0; s < lenmax; s++) {
        // ---- prefetch this step's gx (independent; hides under MMA) ----
        const float* gxr = gxbase + (size_t)s * BB * GG
                         + (size_t)(b0 + bl) * GG + jt * 32 + jl2;
        float2 x0 = *(const float2*)(gxr);
        float2 x1 = *(const float2*)(gxr + 256);
        float2 x2 = *(const float2*)(gxr + 512);
        float2 x3 = *(const float2*)(gxr + 768);

        const uint32_t abase_s = a_base + (uint32_t)((s & 1) * (16 * 132 * 4));

        float acc[2][4];
        #pragma unroll
        for (int nf = 0; nf < 2; nf++)
            #pragma unroll
            for (int q = 0; q < 4; q++) acc[nf][q] = 0.f;

        #pragma unroll 8
        for (int t = 0; t < 16; t++) {    // k = t*16
            uint32_t a[4], bb[4];
            ldsm_x4(a, abase_s + t * 32);
            ldsm_x4(bb, b_base + t * 32);
            mma_bf16(acc[0], a, bb);
            mma_bf16(acc[1], a, bb + 2);
        }

        // stage GEMM result: st[batch 0..15][local col 0..127]
        #pragma unroll
        for (int nf = 0; nf < 2; nf++) {
            int col = w * 16 + nf * 8 + lc * 2;
            *(float2*)&st[lr * 132 + col] = make_float2(acc[nf][0], acc[nf][1]);
            *(float2*)&st[(lr + 8) * 132 + col] = make_float2(acc[nf][2], acc[nf][3]);
        }
        __syncthreads();

        // epilogue: thread handles batch bl, j cols jl2, jl2+1
        float2 v0 = *(const float2*)&st[bl * 132 +       jl2];
        float2 v1 = *(const float2*)&st[bl * 132 +  32 + jl2];
        float2 v2 = *(const float2*)&st[bl * 132 +  64 + jl2];
        float2 v3 = *(const float2*)&st[bl * 132 +  96 + jl2];
        float gi[2] = {v0.x + x0.x, v0.y + x0.y};
        float gf[2] = {v1.x + x1.x, v1.y + x1.y};
        float gg[2] = {v2.x + x2.x, v2.y + x2.y};
        float go[2] = {v3.x + x3.x, v3.y + x3.y};

        float hn[2];
        #pragma unroll
        for (int k = 0; k < 2; k++) {
            float si = sigmoid_fast(gi[k]);
            float sf = sigmoid_fast(gf[k]);
            float so = sigmoid_fast(go[k]);
            float cn = sf * creg[k] + si * tanh_fast(gg[k]);
            creg[k] = cn;
            hn[k] = so * tanh_fast(cn);
        }

        // fp32 h to gmem for emit (fire-and-forget)
        float* hd = hbase + (size_t)(s + 1) * BB * HH
                  + (size_t)(b0 + bl) * HH + jt * 32 + jl2;
        *(float2*)hd = make_float2(hn[0], hn[1]);

        // bf16 h word broadcast into all 8 cluster CTAs' next-phase buffer
        uint32_t pw = pack_bf16(hn[0], hn[1]);
        uint32_t woff = (uint32_t)(((s + 1) & 1) * (16 * 132)
                      + bl * 132 + jt * 16 + (jl2 >> 1));
        uint32_t baddr = hs_addr + woff * 4;
        #pragma unroll
        for (int r = 0; r < 8; r++) {
            uint32_t ra;
            asm("mapa.shared::cluster.u32 %0, %1, %2;" : "=r"(ra) : "r"(baddr), "r"(r));
            asm volatile("st.shared::cluster.b32 [%0], %1;" :: "r"(ra), "r"(pw) : "memory");
        }

        // release our writes / acquire peers' (also acts as CTA barrier)
        CLUSTER_SYNC();
    }
}

// ---------------------------------------------------------------------------
// emit via bf16 MMA (fp32 accumulate) — R8-exact
// ---------------------------------------------------------------------------
#define EMIT_SMEM (2 * 32 * 260 * 4)

__global__ __launch_bounds__(256) void emit_kernel(
    const float* __restrict__ Wout, const float* __restrict__ bout,
    const int* __restrict__ lens)
{
    extern __shared__ uint32_t es[];
    uint32_t* hbw = es;            // [32 s][260 words] bf16x2
    uint32_t* wbw = es + 32 * 260; // [32 t][260 words] bf16x2

    int b = blockIdx.x;
    int s0 = blockIdx.y * 32;
    int len = lens[b];
    if (s0 >= len) return;

    int tid = threadIdx.x;
    for (int idx = tid; idx < 32 * 128; idx += 256) {
        int sl = idx >> 7, q4 = idx & 127;
        int s = s0 + sl;
        float4 v = make_float4(0.f, 0.f, 0.f, 0.f);
        if (s < len) {
            int q = q4 * 4;
            if (q < 256) v = *(const float4*)&g_h[0][s + 1][b][q];
            else         v = *(const float4*)&g_h[1][len - s][b][q - 256];
        }
        hbw[sl * 260 + q4 * 2]     = pack_bf16(v.x, v.y);
        hbw[sl * 260 + q4 * 2 + 1] = pack_bf16(v.z, v.w);
    }
    for (int idx = tid; idx < 32 * 128; idx += 256) {
        int t = idx >> 7, q4 = idx & 127;
        float4 wv = *(const float4*)&Wout[t * 512 + q4 * 4];
        wbw[t * 260 + q4 * 2]     = pack_bf16(wv.x, wv.y);
        wbw[t * 260 + q4 * 2 + 1] = pack_bf16(wv.z, wv.w);
    }
    __syncthreads();

    const int lane = tid & 31, w = tid >> 5;
    const int m2 = w >> 2, n4 = w & 3;
    const int lr = lane >> 2, lc = lane & 3;

    float acc[4] = {0.f, 0.f, 0.f, 0.f};
    const int arow = (m2 * 16 + lr) * 260;
    const int brow = (n4 * 8 + lr) * 260;

    #pragma unroll 8
    for (int kc = 0; kc < 256; kc += 8) {
        uint32_t a[4], bb[2];
        a[0] = hbw[arow + kc + lc];
        a[1] = hbw[arow + 8 * 260 + kc + lc];
        a[2] = hbw[arow + kc + 4 + lc];
        a[3] = hbw[arow + 8 * 260 + kc + 4 + lc];
        bb[0] = wbw[brow + kc + lc];
        bb[1] = wbw[brow + kc + 4 + lc];
        mma_bf16(acc, a, bb);
    }

    int t = n4 * 8 + lc * 2;
    float b0v = bout[t], b1v = bout[t + 1];
    int r0 = s0 + m2 * 16 + lr;
    if (r0 < len)
        *(float2*)&g_emit[b][r0][t] = make_float2(acc[0] + b0v, acc[1] + b1v);
    if (r0 + 8 < len)
        *(float2*)&g_emit[b][r0 + 8][t] = make_float2(acc[2] + b0v, acc[3] + b1v);
}

// ---------------------------------------------------------------------------
// Per-batch CRF with 2-way ILP: one warp handles batches b and b+128
// (lengths sorted desc -> len0 >= len1). The two independent recursions
// interleave in the issue slots, hiding the serial shfl/fma/log chain.
// E = exp(transition) registers shared between the two.
// ---------------------------------------------------------------------------
__global__ void crf_kernel(
    const float* __restrict__ trans,
    const int* __restrict__ tags,
    const int* __restrict__ lens,
    float* __restrict__ out)
{
    int b0 = blockIdx.x;          // 0..127
    int b1 = b0 + 128;
    int j = threadIdx.x;          // 0..31
    __shared__ float tr[32][33];

    int len0 = lens[b0];
    int len1 = lens[b1];
    for (int idx = j; idx < 1024; idx += 32)
        tr[idx >> 5][idx & 31] = trans[idx];
    __syncwarp();

    float E[32];
    #pragma unroll
    for (int i = 0; i < 32; i++) E[i] = __expf(tr[i][j]);

    const int* tg0 = tags + b0 * SS;
    const int* tg1 = tags + b1 * SS;
    const float* em0 = &g_emit[b0][0][0];
    const float* em1 = &g_emit[b1][0][0];

    // real path scores (both batches)
    float rs0 = 0.f, rs1 = 0.f;
    for (int s = j; s < len0; s += 32) {
        int t1 = tg0[s];
        float v = em0[s * 32 + t1];
        if (s > 0) v += tr[tg0[s - 1]][t1];
        rs0 += v;
    }
    for (int s = j; s < len1; s += 32) {
        int t1 = tg1[s];
        float v = em1[s * 32 + t1];
        if (s > 0) v += tr[tg1[s - 1]][t1];
        rs1 += v;
    }
    #pragma unroll
    for (int o = 16; o; o >>= 1) {
        rs0 += __shfl_xor_sync(0xffffffffu, rs0, o);
        rs1 += __shfl_xor_sync(0xffffffffu, rs1, o);
    }

    // forward recursions, interleaved
    float alpha0 = em0[j], alpha1 = em1[j];
    float M0 = alpha0, M1 = alpha1;
    #pragma unroll
    for (int o = 16; o; o >>= 1) {
        M0 = fmaxf(M0, __shfl_xor_sync(0xffffffffu, M0, o));
        M1 = fmaxf(M1, __shfl_xor_sync(0xffffffffu, M1, o));
    }
    float beta0 = __expf(alpha0 - M0);
    float beta1 = __expf(alpha1 - M1);

    for (int s = 1; s < len0; s++) {
        bool run1 = (s < len1);   // uniform across warp
        float a0 = 0.f, a1 = 0.f, a2 = 0.f, a3 = 0.f;
        float c0 = 0.f, c1 = 0.f, c2 = 0.f, c3 = 0.f;
        #pragma unroll
        for (int i = 0; i < 32; i += 4) {
            a0 = fmaf(__shfl_sync(0xffffffffu, beta0, i),     E[i],     a0);
            c0 = fmaf(__shfl_sync(0xffffffffu, beta1, i),     E[i],     c0);
            a1 = fmaf(__shfl_sync(0xffffffffu, beta0, i + 1), E[i + 1], a1);
            c1 = fmaf(__shfl_sync(0xffffffffu, beta1, i + 1), E[i + 1], c1);
            a2 = fmaf(__shfl_sync(0xffffffffu, beta0, i + 2), E[i + 2], a2);
            c2 = fmaf(__shfl_sync(0xffffffffu, beta1, i + 2), E[i + 2], c2);
            a3 = fmaf(__shfl_sync(0xffffffffu, beta0, i + 3), E[i + 3], a3);
            c3 = fmaf(__shfl_sync(0xffffffffu, beta1, i + 3), E[i + 3], c3);
        }
        alpha0 = M0 + __logf((a0 + a1) + (a2 + a3)) + em0[s * 32 + j];
        if (run1)
            alpha1 = M1 + __logf((c0 + c1) + (c2 + c3)) + em1[s * 32 + j];
        if ((s & 3) == 0) {
            float m0 = alpha0, m1 = alpha1;
            #pragma unroll
            for (int o = 16; o; o >>= 1) {
                m0 = fmaxf(m0, __shfl_xor_sync(0xffffffffu, m0, o));
                m1 = fmaxf(m1, __shfl_xor_sync(0xffffffffu, m1, o));
            }
            M0 = m0;
            M1 = m1;
        }
        beta0 = __expf(alpha0 - M0);
        beta1 = __expf(alpha1 - M1);
    }

    // final logsumexp from alpha directly (no stale-beta hazard)
    float m0 = alpha0, m1 = alpha1;
    #pragma unroll
    for (int o = 16; o; o >>= 1) {
        m0 = fmaxf(m0, __shfl_xor_sync(0xffffffffu, m0, o));
        m1 = fmaxf(m1, __shfl_xor_sync(0xffffffffu, m1, o));
    }
    float e0 = __expf(alpha0 - m0);
    float e1 = __expf(alpha1 - m1);
    #pragma unroll
    for (int o = 16; o; o >>= 1) {
        e0 += __shfl_xor_sync(0xffffffffu, e0, o);
        e1 += __shfl_xor_sync(0xffffffffu, e1, o);
    }
    if (j == 0) {
        out[b0] = (m0 + __logf(e0)) - rs0;
        out[b1] = (m1 + __logf(e1)) - rs1;
    }
}

// ---------------------------------------------------------------------------
extern "C" void kernel_launch(void* const* d_in, const int* in_sizes, int n_in,
                              void* d_out, int out_size)
{
    const float* embed = (const float*)d_in[0];
    const float* Wih_f = (const float*)d_in[1];
    const float* Whh_f = (const float*)d_in[2];
    const float* bih_f = (const float*)d_in[3];
    const float* bhh_f = (const float*)d_in[4];
    const float* Wih_b = (const float*)d_in[5];
    const float* Whh_b = (const float*)d_in[6];
    const float* bih_b = (const float*)d_in[7];
    const float* bhh_b = (const float*)d_in[8];
    const float* Wout  = (const float*)d_in[9];
    const float* bout  = (const float*)d_in[10];
    const float* trans = (const float*)d_in[11];
    const int* sent = (const int*)d_in[12];
    const int* tags = (const int*)d_in[13];
    const int* lens = (const int*)d_in[14];
    float* out = (float*)d_out;

    cudaFuncSetAttribute(gemm_inproj_tc,
                         cudaFuncAttributeMaxDynamicSharedMemorySize, INP_SMEM);
    cudaFuncSetAttribute(lstm_persist,
                         cudaFuncAttributeMaxDynamicSharedMemorySize, LSTM_SMEM);
    cudaFuncSetAttribute(emit_kernel,
                         cudaFuncAttributeMaxDynamicSharedMemorySize, EMIT_SMEM);

    dim3 g1(2048, 8, 2);
    gemm_inproj_tc<<<g1, 256, INP_SMEM>>>(embed, Wih_f, Wih_b,
                                          bih_f, bhh_f, bih_b, bhh_b, sent, lens);

    dim3 gl(8, 32);
    lstm_persist<<<gl, 256, LSTM_SMEM>>>(Whh_f, Whh_b, lens);

    dim3 ge(256, 16);
    emit_kernel<<<ge, 256, EMIT_SMEM>>>(Wout, bout, lens);

    crf_kernel<<<128, 32>>>(trans, tags, lens, out);
}

// round 15
// speedup vs baseline: 1.1438x; 1.1438x over previous
#include <cuda_runtime.h>
#include <cuda_bf16.h>
#include <math.h>
#include <stdint.h>

#define SS 512
#define BB 256
#define EE 256
#define HH 256
#define GG 1024   // 4*H
#define TT 32

// Scratch (device globals: allocation-free contract)
__device__ float g_gx[2][SS][BB][GG];            // pre-activations
__device__ uint32_t g_hb[2][SS + 1][BB][HH / 2]; // bf16x2 hidden states (for emit)
__device__ float g_emit[BB][SS][TT];             // emission scores

// ---------------------------------------------------------------------------
__device__ __forceinline__ void mma_bf16(float d[4], const uint32_t a[4], const uint32_t b[2]) {
    asm volatile(
        "mma.sync.aligned.m16n8k16.row.col.f32.bf16.bf16.f32 "
        "{%0,%1,%2,%3}, {%4,%5,%6,%7}, {%8,%9}, {%0,%1,%2,%3};\n"
        : "+f"(d[0]), "+f"(d[1]), "+f"(d[2]), "+f"(d[3])
        : "r"(a[0]), "r"(a[1]), "r"(a[2]), "r"(a[3]), "r"(b[0]), "r"(b[1]));
}

__device__ __forceinline__ void ldsm_x4(uint32_t r[4], uint32_t addr) {
    asm volatile("ldmatrix.sync.aligned.m8n8.x4.shared.b16 {%0,%1,%2,%3}, [%4];"
        : "=r"(r[0]), "=r"(r[1]), "=r"(r[2]), "=r"(r[3]) : "r"(addr));
}

__device__ __forceinline__ uint32_t pack_bf16(float lo, float hi) {
    __nv_bfloat162 t = __floats2bfloat162_rn(lo, hi);
    return *(uint32_t*)&t;
}

__device__ __forceinline__ uint32_t smem_u32(const void* p) {
    uint32_t a;
    asm("{ .reg .u64 t; cvta.to.shared.u64 t, %1; cvt.u32.u64 %0, t; }"
        : "=r"(a) : "l"(p));
    return a;
}

__device__ __forceinline__ float tanh_fast(float x) {
    float y;
    asm("tanh.approx.f32 %0, %1;" : "=f"(y) : "f"(x));
    return y;
}
__device__ __forceinline__ float sigmoid_fast(float x) {
    return fmaf(tanh_fast(0.5f * x), 0.5f, 0.5f);
}

#define CLUSTER_SYNC() do { \
    asm volatile("barrier.cluster.arrive.aligned;" ::: "memory"); \
    asm volatile("barrier.cluster.wait.aligned;" ::: "memory"); \
} while (0)

// ---------------------------------------------------------------------------
// Input projection with fused embedding gather (bf16 MMA + ldmatrix):
//   gx[dir][s][b][n] = sum_e embed[row][e] * W_ih[n][e] + b_ih[n] + b_hh[n]
// Block tile: 64 (batch rows at one s) x 128 (gate cols), K=256 smem-resident.
// (R8-exact)
// ---------------------------------------------------------------------------
#define INP_SMEM ((64 + 128) * 132 * 4)

__global__ __launch_bounds__(256) void gemm_inproj_tc(
    const float* __restrict__ embed,
    const float* __restrict__ Wf, const float* __restrict__ Wb,
    const float* __restrict__ bih_f, const float* __restrict__ bhh_f,
    const float* __restrict__ bih_b, const float* __restrict__ bhh_b,
    const int* __restrict__ sent, const int* __restrict__ lens)
{
    extern __shared__ uint32_t smw[];
    uint32_t* au = smw;              // A: 64 rows x 132 words (bf16x2)
    uint32_t* wu = smw + 64 * 132;   // W: 128 cols x 132 words
    __shared__ int rowid[64];

    const int dir = blockIdx.z;
    const int m0 = blockIdx.x * 64;
    const int n0 = blockIdx.y * 128;
    const int s  = m0 >> 8;
    const int bf = m0 & 255;
    if (s >= lens[bf]) return;   // lengths sorted desc

    const int tid = threadIdx.x;
    if (tid < 64) {
        int b = bf + tid;
        int len = lens[b];
        int ss = (dir == 1 && s < len) ? (len - 1 - s) : s;
        rowid[tid] = sent[b * SS + ss];
    }
    __syncthreads();

    for (int idx = tid; idx < 64 * 64; idx += 256) {
        int r = idx >> 6, q4 = idx & 63;
        float4 v = *(const float4*)(embed + (size_t)rowid[r] * EE + q4 * 4);
        au[r * 132 + q4 * 2]     = pack_bf16(v.x, v.y);
        au[r * 132 + q4 * 2 + 1] = pack_bf16(v.z, v.w);
    }
    const float* __restrict__ W = dir ? Wb : Wf;
    for (int idx = tid; idx < 128 * 64; idx += 256) {
        int c = idx >> 6, q4 = idx & 63;
        float4 w = *(const float4*)(W + (size_t)(n0 + c) * EE + q4 * 4);
        wu[c * 132 + q4 * 2]     = pack_bf16(w.x, w.y);
        wu[c * 132 + q4 * 2 + 1] = pack_bf16(w.z, w.w);
    }
    __syncthreads();

    const int lane = tid & 31, wid = tid >> 5;
    const int wm = wid & 3, wn = wid >> 2;
    const int lr = lane >> 2, lc = lane & 3;

    float acc[8][4];
    #pragma unroll
    for (int i = 0; i < 8; i++)
        #pragma unroll
        for (int j = 0; j < 4; j++) acc[i][j] = 0.f;

    const uint32_t au_addr = smem_u32(au);
    const uint32_t wu_addr = smem_u32(wu);
    const uint32_t a_base = au_addr +
        (((wm * 16 + (lane & 15)) * 132 + ((lane >> 4) << 2)) << 2);
    const uint32_t b_base = wu_addr +
        ((((wn * 64) + (lane & 7) + ((lane >> 4) << 3)) * 132 + (((lane >> 3) & 1) << 2)) << 2);

    #pragma unroll 4
    for (int t = 0; t < 16; t++) {        // k = t*16
        uint32_t a[4];
        ldsm_x4(a, a_base + t * 32);
        #pragma unroll
        for (int p = 0; p < 4; p++) {
            uint32_t bb[4];
            ldsm_x4(bb, b_base + p * (16 * 132 * 4) + t * 32);
            mma_bf16(acc[p * 2],     a, bb);
            mma_bf16(acc[p * 2 + 1], a, bb + 2);
        }
    }

    const float* bi = dir ? bih_b : bih_f;
    const float* bh = dir ? bhh_b : bhh_f;
    float* gxp = &g_gx[dir][0][0][0];
    const int row = m0 + wm * 16 + lr;
    #pragma unroll
    for (int nf = 0; nf < 8; nf++) {
        int n = n0 + wn * 64 + nf * 8 + lc * 2;
        float b0v = bi[n] + bh[n];
        float b1v = bi[n + 1] + bh[n + 1];
        *(float2*)(gxp + (size_t)row * GG + n) =
            make_float2(acc[nf][0] + b0v, acc[nf][1] + b1v);
        *(float2*)(gxp + (size_t)(row + 8) * GG + n) =
            make_float2(acc[nf][2] + b0v, acc[nf][3] + b1v);
    }
}

// ---------------------------------------------------------------------------
// Persistent bidirectional LSTM (R8-exact structure): clusters of 8 CTAs per
// (dir, 16-batch tile), 256 CTAs -> 2 clusters/SM. Only change vs R8: h is
// stored to gmem as bf16x2 (the already-computed DSMEM word) instead of fp32.
// ---------------------------------------------------------------------------
#define LSTM_ST_WORDS (16 * 132)           // fp32 staging [16][132]
#define LSTM_WS_WORDS (128 * 132)          // bf16x2 weights [128 cols][132]
#define LSTM_HS_WORDS (2 * 16 * 132)       // bf16x2 h, double-buffered
#define LSTM_SMEM ((LSTM_ST_WORDS + LSTM_WS_WORDS + LSTM_HS_WORDS) * 4)

__global__ __launch_bounds__(256, 2) __cluster_dims__(8, 1, 1)
void lstm_persist(
    const float* __restrict__ Whh_f, const float* __restrict__ Whh_b,
    const int* __restrict__ lens)
{
    extern __shared__ float smf[];
    float* st = smf;                                    // [16][132] fp32
    uint32_t* wsu = (uint32_t*)(smf + LSTM_ST_WORDS);   // [128][132] bf16x2
    uint32_t* hsu = wsu + LSTM_WS_WORDS;                // [2][16][132] bf16x2

    const int tid = threadIdx.x;
    const int jt  = blockIdx.x;          // cluster rank 0..7 -> j-cols jt*32..
    const int dir = blockIdx.y >> 4;
    const int mb  = blockIdx.y & 15;
    const int b0  = mb * 16;
    const int lenmax = lens[b0];         // same for whole cluster

    // Load bf16 weights. Local col c (0..127): gate g=c>>5, j=jt*32+(c&31)
    const float* __restrict__ W = dir ? Whh_b : Whh_f;
    for (int idx = tid; idx < 128 * 64; idx += 256) {
        int c = idx >> 6, q4 = idx & 63;
        int n = ((c >> 5) << 8) + jt * 32 + (c & 31);
        float4 w = *(const float4*)(W + (size_t)n * HH + q4 * 4);
        wsu[c * 132 + q4 * 2]     = pack_bf16(w.x, w.y);
        wsu[c * 132 + q4 * 2 + 1] = pack_bf16(w.z, w.w);
    }
    for (int idx = tid; idx < LSTM_HS_WORDS; idx += 256) hsu[idx] = 0u;

    const int lane = tid & 31, w = tid >> 5;
    const int lr = lane >> 2, lc = lane & 3;
    const int bl  = tid >> 4;            // epilogue batch row 0..15
    const int jl2 = (tid & 15) * 2;      // epilogue j pair

    float creg[2] = {0.f, 0.f};

    const float* gxbase = &g_gx[dir][0][0][0];
    uint32_t* hbbase = &g_hb[dir][0][0][0];
    const uint32_t hs_addr = smem_u32(hsu);
    const uint32_t ws_addr = smem_u32(wsu);
    const uint32_t a_base = hs_addr +
        ((((lane & 15)) * 132 + ((lane >> 4) << 2)) << 2);
    const uint32_t b_base = ws_addr +
        ((((w * 16) + (lane & 7) + ((lane >> 4) << 3)) * 132 + (((lane >> 3) & 1) << 2)) << 2);

    __syncthreads();     // weights + zeroed h ready
    // peers must see our zeroed h buffers before their step-0 remote writes
    CLUSTER_SYNC();

    for (int s = 0; s < lenmax; s++) {
        // ---- prefetch this step's gx (independent; hides under MMA) ----
        const float* gxr = gxbase + (size_t)s * BB * GG
                         + (size_t)(b0 + bl) * GG + jt * 32 + jl2;
        float2 x0 = *(const float2*)(gxr);
        float2 x1 = *(const float2*)(gxr + 256);
        float2 x2 = *(const float2*)(gxr + 512);
        float2 x3 = *(const float2*)(gxr + 768);

        const uint32_t abase_s = a_base + (uint32_t)((s & 1) * (16 * 132 * 4));

        float acc[2][4];
        #pragma unroll
        for (int nf = 0; nf < 2; nf++)
            #pragma unroll
            for (int q = 0; q < 4; q++) acc[nf][q] = 0.f;

        #pragma unroll 8
        for (int t = 0; t < 16; t++) {    // k = t*16
            uint32_t a[4], bb[4];
            ldsm_x4(a, abase_s + t * 32);
            ldsm_x4(bb, b_base + t * 32);
            mma_bf16(acc[0], a, bb);
            mma_bf16(acc[1], a, bb + 2);
        }

        // stage GEMM result: st[batch 0..15][local col 0..127]
        #pragma unroll
        for (int nf = 0; nf < 2; nf++) {
            int col = w * 16 + nf * 8 + lc * 2;
            *(float2*)&st[lr * 132 + col] = make_float2(acc[nf][0], acc[nf][1]);
            *(float2*)&st[(lr + 8) * 132 + col] = make_float2(acc[nf][2], acc[nf][3]);
        }
        __syncthreads();

        // epilogue: thread handles batch bl, j cols jl2, jl2+1
        float2 v0 = *(const float2*)&st[bl * 132 +       jl2];
        float2 v1 = *(const float2*)&st[bl * 132 +  32 + jl2];
        float2 v2 = *(const float2*)&st[bl * 132 +  64 + jl2];
        float2 v3 = *(const float2*)&st[bl * 132 +  96 + jl2];
        float gi[2] = {v0.x + x0.x, v0.y + x0.y};
        float gf[2] = {v1.x + x1.x, v1.y + x1.y};
        float gg[2] = {v2.x + x2.x, v2.y + x2.y};
        float go[2] = {v3.x + x3.x, v3.y + x3.y};

        float hn[2];
        #pragma unroll
        for (int k = 0; k < 2; k++) {
            float si = sigmoid_fast(gi[k]);
            float sf = sigmoid_fast(gf[k]);
            float so = sigmoid_fast(go[k]);
            float cn = sf * creg[k] + si * tanh_fast(gg[k]);
            creg[k] = cn;
            hn[k] = so * tanh_fast(cn);
        }

        // bf16 h word: reused for BOTH the gmem store (emit) and DSMEM fan-out
        uint32_t pw = pack_bf16(hn[0], hn[1]);

        // bf16 h to gmem for emit (fire-and-forget, STG.32)
        hbbase[(size_t)(s + 1) * BB * (HH / 2)
               + (size_t)(b0 + bl) * (HH / 2) + jt * 16 + (jl2 >> 1)] = pw;

        // broadcast into all 8 cluster CTAs' next-phase buffer
        uint32_t woff = (uint32_t)(((s + 1) & 1) * (16 * 132)
                      + bl * 132 + jt * 16 + (jl2 >> 1));
        uint32_t baddr = hs_addr + woff * 4;
        #pragma unroll
        for (int r = 0; r < 8; r++) {
            uint32_t ra;
            asm("mapa.shared::cluster.u32 %0, %1, %2;" : "=r"(ra) : "r"(baddr), "r"(r));
            asm volatile("st.shared::cluster.b32 [%0], %1;" :: "r"(ra), "r"(pw) : "memory");
        }

        // release our writes / acquire peers' (also acts as CTA barrier)
        CLUSTER_SYNC();
    }
}

// ---------------------------------------------------------------------------
// emit via bf16 MMA (fp32 accumulate). h is now ALREADY bf16 in gmem:
// loads are raw uint4 copies (half the traffic, no pack).
// emit[b][s][t] = b_out[t] + h_f[s].Wout[t][0:256] + h_b[len-1-s].Wout[t][256:512]
// ---------------------------------------------------------------------------
#define EMIT_SMEM (2 * 32 * 260 * 4)

__global__ __launch_bounds__(256) void emit_kernel(
    const float* __restrict__ Wout, const float* __restrict__ bout,
    const int* __restrict__ lens)
{
    extern __shared__ uint32_t es[];
    uint32_t* hbw = es;            // [32 s][260 words] bf16x2
    uint32_t* wbw = es + 32 * 260; // [32 t][260 words] bf16x2

    int b = blockIdx.x;
    int s0 = blockIdx.y * 32;
    int len = lens[b];
    if (s0 >= len) return;

    int tid = threadIdx.x;
    // h rows: 256 words per s-row = 128 fwd + 128 bwd; load as uint4 (4 words)
    for (int idx = tid; idx < 32 * 64; idx += 256) {
        int sl = idx >> 6;
        int qw = (idx & 63) * 4;     // word offset 0..252
        int s = s0 + sl;
        uint4 v = make_uint4(0u, 0u, 0u, 0u);
        if (s < len) {
            if (qw < 128) v = *(const uint4*)&g_hb[0][s + 1][b][qw];
            else          v = *(const uint4*)&g_hb[1][len - s][b][qw - 128];
        }
        *(uint4*)&hbw[sl * 260 + qw] = v;
    }
    for (int idx = tid; idx < 32 * 128; idx += 256) {
        int t = idx >> 7, q4 = idx & 127;
        float4 wv = *(const float4*)&Wout[t * 512 + q4 * 4];
        wbw[t * 260 + q4 * 2]     = pack_bf16(wv.x, wv.y);
        wbw[t * 260 + q4 * 2 + 1] = pack_bf16(wv.z, wv.w);
    }
    __syncthreads();

    const int lane = tid & 31, w = tid >> 5;
    const int m2 = w >> 2, n4 = w & 3;
    const int lr = lane >> 2, lc = lane & 3;

    float acc[4] = {0.f, 0.f, 0.f, 0.f};
    const int arow = (m2 * 16 + lr) * 260;
    const int brow = (n4 * 8 + lr) * 260;

    #pragma unroll 8
    for (int kc = 0; kc < 256; kc += 8) {
        uint32_t a[4], bb[2];
        a[0] = hbw[arow + kc + lc];
        a[1] = hbw[arow + 8 * 260 + kc + lc];
        a[2] = hbw[arow + kc + 4 + lc];
        a[3] = hbw[arow + 8 * 260 + kc + 4 + lc];
        bb[0] = wbw[brow + kc + lc];
        bb[1] = wbw[brow + kc + 4 + lc];
        mma_bf16(acc, a, bb);
    }

    int t = n4 * 8 + lc * 2;
    float b0v = bout[t], b1v = bout[t + 1];
    int r0 = s0 + m2 * 16 + lr;
    if (r0 < len)
        *(float2*)&g_emit[b][r0][t] = make_float2(acc[0] + b0v, acc[1] + b1v);
    if (r0 + 8 < len)
        *(float2*)&g_emit[b][r0 + 8][t] = make_float2(acc[2] + b0v, acc[3] + b1v);
}

// ---------------------------------------------------------------------------
// Per-batch CRF, one warp per b (R8 configuration). E=exp(trans) in registers,
// 4-way split dot chain, max rescale every 8 steps.
// ---------------------------------------------------------------------------
__global__ void crf_kernel(
    const float* __restrict__ trans,
    const int* __restrict__ tags,
    const int* __restrict__ lens,
    float* __restrict__ out)
{
    int b = blockIdx.x;
    int j = threadIdx.x;   // 0..31
    __shared__ float tr[32][33];

    int len = lens[b];
    for (int idx = j; idx < 1024; idx += 32)
        tr[idx >> 5][idx & 31] = trans[idx];
    __syncwarp();

    float E[32];
    #pragma unroll
    for (int i = 0; i < 32; i++) E[i] = __expf(tr[i][j]);

    const int* tg = tags + b * SS;
    const float* em = &g_emit[b][0][0];

    float rs = 0.f;
    for (int s = j; s < len; s += 32) {
        int t1 = tg[s];
        float v = em[s * 32 + t1];
        if (s > 0) v += tr[tg[s - 1]][t1];
        rs += v;
    }
    #pragma unroll
    for (int o = 16; o; o >>= 1) rs += __shfl_xor_sync(0xffffffffu, rs, o);

    float alpha = em[j];
    float M = alpha;
    #pragma unroll
    for (int o = 16; o; o >>= 1) M = fmaxf(M, __shfl_xor_sync(0xffffffffu, M, o));
    float beta = __expf(alpha - M);

    for (int s = 1; s < len; s++) {
        float d0 = 0.f, d1 = 0.f, d2 = 0.f, d3 = 0.f;
        #pragma unroll
        for (int i = 0; i < 32; i += 4) {
            d0 = fmaf(__shfl_sync(0xffffffffu, beta, i),     E[i],     d0);
            d1 = fmaf(__shfl_sync(0xffffffffu, beta, i + 1), E[i + 1], d1);
            d2 = fmaf(__shfl_sync(0xffffffffu, beta, i + 2), E[i + 2], d2);
            d3 = fmaf(__shfl_sync(0xffffffffu, beta, i + 3), E[i + 3], d3);
        }
        alpha = M + __logf((d0 + d1) + (d2 + d3)) + em[s * 32 + j];
        if ((s & 7) == 0) {
            float m2 = alpha;
            #pragma unroll
            for (int o = 16; o; o >>= 1)
                m2 = fmaxf(m2, __shfl_xor_sync(0xffffffffu, m2, o));
            M = m2;
        }
        beta = __expf(alpha - M);
    }

    // final logsumexp from alpha directly
    float m = alpha;
    #pragma unroll
    for (int o = 16; o; o >>= 1) m = fmaxf(m, __shfl_xor_sync(0xffffffffu, m, o));
    float e = __expf(alpha - m);
    #pragma unroll
    for (int o = 16; o; o >>= 1) e += __shfl_xor_sync(0xffffffffu, e, o);
    float logz = m + __logf(e);
    if (j == 0) out[b] = logz - rs;
}

// ---------------------------------------------------------------------------
extern "C" void kernel_launch(void* const* d_in, const int* in_sizes, int n_in,
                              void* d_out, int out_size)
{
    const float* embed = (const float*)d_in[0];
    const float* Wih_f = (const float*)d_in[1];
    const float* Whh_f = (const float*)d_in[2];
    const float* bih_f = (const float*)d_in[3];
    const float* bhh_f = (const float*)d_in[4];
    const float* Wih_b = (const float*)d_in[5];
    const float* Whh_b = (const float*)d_in[6];
    const float* bih_b = (const float*)d_in[7];
    const float* bhh_b = (const float*)d_in[8];
    const float* Wout  = (const float*)d_in[9];
    const float* bout  = (const float*)d_in[10];
    const float* trans = (const float*)d_in[11];
    const int* sent = (const int*)d_in[12];
    const int* tags = (const int*)d_in[13];
    const int* lens = (const int*)d_in[14];
    float* out = (float*)d_out;

    cudaFuncSetAttribute(gemm_inproj_tc,
                         cudaFuncAttributeMaxDynamicSharedMemorySize, INP_SMEM);
    cudaFuncSetAttribute(lstm_persist,
                         cudaFuncAttributeMaxDynamicSharedMemorySize, LSTM_SMEM);
    cudaFuncSetAttribute(emit_kernel,
                         cudaFuncAttributeMaxDynamicSharedMemorySize, EMIT_SMEM);

    dim3 g1(2048, 8, 2);
    gemm_inproj_tc<<<g1, 256, INP_SMEM>>>(embed, Wih_f, Wih_b,
                                          bih_f, bhh_f, bih_b, bhh_b, sent, lens);

    dim3 gl(8, 32);
    lstm_persist<<<gl, 256, LSTM_SMEM>>>(Whh_f, Whh_b, lens);

    dim3 ge(256, 16);
    emit_kernel<<<ge, 256, EMIT_SMEM>>>(Wout, bout, lens);

    crf_kernel<<<256, 32>>>(trans, tags, lens, out);
}

// round 16
// speedup vs baseline: 1.1477x; 1.0034x over previous
#include <cuda_runtime.h>
#include <cuda_bf16.h>
#include <math.h>
#include <stdint.h>

#define SS 512
#define BB 256
#define EE 256
#define HH 256
#define GG 1024   // 4*H
#define TT 32

// Scratch (device globals: allocation-free contract)
__device__ float g_gx[2][SS][BB][GG];            // pre-activations
__device__ uint32_t g_hb[2][SS + 1][BB][HH / 2]; // bf16x2 hidden states (for emit)
__device__ float g_emit[BB][SS][TT];             // emission scores

// ---------------------------------------------------------------------------
__device__ __forceinline__ void mma_bf16(float d[4], const uint32_t a[4], const uint32_t b[2]) {
    asm volatile(
        "mma.sync.aligned.m16n8k16.row.col.f32.bf16.bf16.f32 "
        "{%0,%1,%2,%3}, {%4,%5,%6,%7}, {%8,%9}, {%0,%1,%2,%3};\n"
        : "+f"(d[0]), "+f"(d[1]), "+f"(d[2]), "+f"(d[3])
        : "r"(a[0]), "r"(a[1]), "r"(a[2]), "r"(a[3]), "r"(b[0]), "r"(b[1]));
}

__device__ __forceinline__ void ldsm_x4(uint32_t r[4], uint32_t addr) {
    asm volatile("ldmatrix.sync.aligned.m8n8.x4.shared.b16 {%0,%1,%2,%3}, [%4];"
        : "=r"(r[0]), "=r"(r[1]), "=r"(r[2]), "=r"(r[3]) : "r"(addr));
}

__device__ __forceinline__ uint32_t pack_bf16(float lo, float hi) {
    __nv_bfloat162 t = __floats2bfloat162_rn(lo, hi);
    return *(uint32_t*)&t;
}

__device__ __forceinline__ uint32_t smem_u32(const void* p) {
    uint32_t a;
    asm("{ .reg .u64 t; cvta.to.shared.u64 t, %1; cvt.u32.u64 %0, t; }"
        : "=r"(a) : "l"(p));
    return a;
}

__device__ __forceinline__ float tanh_fast(float x) {
    float y;
    asm("tanh.approx.f32 %0, %1;" : "=f"(y) : "f"(x));
    return y;
}
__device__ __forceinline__ float sigmoid_fast(float x) {
    return fmaf(tanh_fast(0.5f * x), 0.5f, 0.5f);
}

#define CLUSTER_SYNC() do { \
    asm volatile("barrier.cluster.arrive.aligned;" ::: "memory"); \
    asm volatile("barrier.cluster.wait.aligned;" ::: "memory"); \
} while (0)
#define CLUSTER_ARRIVE() \
    asm volatile("barrier.cluster.arrive.aligned;" ::: "memory")
#define CLUSTER_WAIT() \
    asm volatile("barrier.cluster.wait.aligned;" ::: "memory")

// ---------------------------------------------------------------------------
// Input projection with fused embedding gather (bf16 MMA + ldmatrix):
//   gx[dir][s][b][n] = sum_e embed[row][e] * W_ih[n][e] + b_ih[n] + b_hh[n]
// Block tile: 64 (batch rows at one s) x 128 (gate cols), K=256 smem-resident.
// (R8-exact)
// ---------------------------------------------------------------------------
#define INP_SMEM ((64 + 128) * 132 * 4)

__global__ __launch_bounds__(256) void gemm_inproj_tc(
    const float* __restrict__ embed,
    const float* __restrict__ Wf, const float* __restrict__ Wb,
    const float* __restrict__ bih_f, const float* __restrict__ bhh_f,
    const float* __restrict__ bih_b, const float* __restrict__ bhh_b,
    const int* __restrict__ sent, const int* __restrict__ lens)
{
    extern __shared__ uint32_t smw[];
    uint32_t* au = smw;              // A: 64 rows x 132 words (bf16x2)
    uint32_t* wu = smw + 64 * 132;   // W: 128 cols x 132 words
    __shared__ int rowid[64];

    const int dir = blockIdx.z;
    const int m0 = blockIdx.x * 64;
    const int n0 = blockIdx.y * 128;
    const int s  = m0 >> 8;
    const int bf = m0 & 255;
    if (s >= lens[bf]) return;   // lengths sorted desc

    const int tid = threadIdx.x;
    if (tid < 64) {
        int b = bf + tid;
        int len = lens[b];
        int ss = (dir == 1 && s < len) ? (len - 1 - s) : s;
        rowid[tid] = sent[b * SS + ss];
    }
    __syncthreads();

    for (int idx = tid; idx < 64 * 64; idx += 256) {
        int r = idx >> 6, q4 = idx & 63;
        float4 v = *(const float4*)(embed + (size_t)rowid[r] * EE + q4 * 4);
        au[r * 132 + q4 * 2]     = pack_bf16(v.x, v.y);
        au[r * 132 + q4 * 2 + 1] = pack_bf16(v.z, v.w);
    }
    const float* __restrict__ W = dir ? Wb : Wf;
    for (int idx = tid; idx < 128 * 64; idx += 256) {
        int c = idx >> 6, q4 = idx & 63;
        float4 w = *(const float4*)(W + (size_t)(n0 + c) * EE + q4 * 4);
        wu[c * 132 + q4 * 2]     = pack_bf16(w.x, w.y);
        wu[c * 132 + q4 * 2 + 1] = pack_bf16(w.z, w.w);
    }
    __syncthreads();

    const int lane = tid & 31, wid = tid >> 5;
    const int wm = wid & 3, wn = wid >> 2;
    const int lr = lane >> 2, lc = lane & 3;

    float acc[8][4];
    #pragma unroll
    for (int i = 0; i < 8; i++)
        #pragma unroll
        for (int j = 0; j < 4; j++) acc[i][j] = 0.f;

    const uint32_t au_addr = smem_u32(au);
    const uint32_t wu_addr = smem_u32(wu);
    const uint32_t a_base = au_addr +
        (((wm * 16 + (lane & 15)) * 132 + ((lane >> 4) << 2)) << 2);
    const uint32_t b_base = wu_addr +
        ((((wn * 64) + (lane & 7) + ((lane >> 4) << 3)) * 132 + (((lane >> 3) & 1) << 2)) << 2);

    #pragma unroll 4
    for (int t = 0; t < 16; t++) {        // k = t*16
        uint32_t a[4];
        ldsm_x4(a, a_base + t * 32);
        #pragma unroll
        for (int p = 0; p < 4; p++) {
            uint32_t bb[4];
            ldsm_x4(bb, b_base + p * (16 * 132 * 4) + t * 32);
            mma_bf16(acc[p * 2],     a, bb);
            mma_bf16(acc[p * 2 + 1], a, bb + 2);
        }
    }

    const float* bi = dir ? bih_b : bih_f;
    const float* bh = dir ? bhh_b : bhh_f;
    float* gxp = &g_gx[dir][0][0][0];
    const int row = m0 + wm * 16 + lr;
    #pragma unroll
    for (int nf = 0; nf < 8; nf++) {
        int n = n0 + wn * 64 + nf * 8 + lc * 2;
        float b0v = bi[n] + bh[n];
        float b1v = bi[n + 1] + bh[n + 1];
        *(float2*)(gxp + (size_t)row * GG + n) =
            make_float2(acc[nf][0] + b0v, acc[nf][1] + b1v);
        *(float2*)(gxp + (size_t)(row + 8) * GG + n) =
            make_float2(acc[nf][2] + b0v, acc[nf][3] + b1v);
    }
}

// ---------------------------------------------------------------------------
// Persistent bidirectional LSTM (R15 structure + split cluster barrier):
// clusters of 8 CTAs per (dir, 16-batch tile), 256 CTAs -> 2 clusters/SM.
// Per step: WAIT (peers' h visible) -> ldsm/MMA -> staging -> epilogue (gx
// preloaded last iteration) -> DSMEM fan-out -> ARRIVE -> off-chain gmem h
// store + gx[s+1] prefetch (overlaps barrier skew) -> loop.
// ---------------------------------------------------------------------------
#define LSTM_ST_WORDS (16 * 132)           // fp32 staging [16][132]
#define LSTM_WS_WORDS (128 * 132)          // bf16x2 weights [128 cols][132]
#define LSTM_HS_WORDS (2 * 16 * 132)       // bf16x2 h, double-buffered
#define LSTM_SMEM ((LSTM_ST_WORDS + LSTM_WS_WORDS + LSTM_HS_WORDS) * 4)

__global__ __launch_bounds__(256, 2) __cluster_dims__(8, 1, 1)
void lstm_persist(
    const float* __restrict__ Whh_f, const float* __restrict__ Whh_b,
    const int* __restrict__ lens)
{
    extern __shared__ float smf[];
    float* st = smf;                                    // [16][132] fp32
    uint32_t* wsu = (uint32_t*)(smf + LSTM_ST_WORDS);   // [128][132] bf16x2
    uint32_t* hsu = wsu + LSTM_WS_WORDS;                // [2][16][132] bf16x2

    const int tid = threadIdx.x;
    const int jt  = blockIdx.x;          // cluster rank 0..7 -> j-cols jt*32..
    const int dir = blockIdx.y >> 4;
    const int mb  = blockIdx.y & 15;
    const int b0  = mb * 16;
    const int lenmax = lens[b0];         // same for whole cluster

    // Load bf16 weights. Local col c (0..127): gate g=c>>5, j=jt*32+(c&31)
    const float* __restrict__ W = dir ? Whh_b : Whh_f;
    for (int idx = tid; idx < 128 * 64; idx += 256) {
        int c = idx >> 6, q4 = idx & 63;
        int n = ((c >> 5) << 8) + jt * 32 + (c & 31);
        float4 w = *(const float4*)(W + (size_t)n * HH + q4 * 4);
        wsu[c * 132 + q4 * 2]     = pack_bf16(w.x, w.y);
        wsu[c * 132 + q4 * 2 + 1] = pack_bf16(w.z, w.w);
    }
    for (int idx = tid; idx < LSTM_HS_WORDS; idx += 256) hsu[idx] = 0u;

    const int lane = tid & 31, w = tid >> 5;
    const int lr = lane >> 2, lc = lane & 3;
    const int bl  = tid >> 4;            // epilogue batch row 0..15
    const int jl2 = (tid & 15) * 2;      // epilogue j pair

    float creg[2] = {0.f, 0.f};

    const float* gxbase = &g_gx[dir][0][0][0];
    uint32_t* hbbase = &g_hb[dir][0][0][0];
    const uint32_t hs_addr = smem_u32(hsu);
    const uint32_t ws_addr = smem_u32(wsu);
    const uint32_t a_base = hs_addr +
        ((((lane & 15)) * 132 + ((lane >> 4) << 2)) << 2);
    const uint32_t b_base = ws_addr +
        ((((w * 16) + (lane & 7) + ((lane >> 4) << 3)) * 132 + (((lane >> 3) & 1) << 2)) << 2);

    const float* gx_td = gxbase + (size_t)(b0 + bl) * GG + jt * 32 + jl2;

    __syncthreads();     // weights + zeroed h ready
    // peers must see our zeroed h buffers before their step-0 remote writes
    CLUSTER_SYNC();

    // prefetch gx[0] into registers
    float2 x0 = *(const float2*)(gx_td);
    float2 x1 = *(const float2*)(gx_td + 256);
    float2 x2 = *(const float2*)(gx_td + 512);
    float2 x3 = *(const float2*)(gx_td + 768);

    CLUSTER_ARRIVE();    // primer: first in-loop WAIT pairs with this

    for (int s = 0; s < lenmax; s++) {
        CLUSTER_WAIT();  // all peers' h writes for step s are visible

        const uint32_t abase_s = a_base + (uint32_t)((s & 1) * (16 * 132 * 4));

        float acc[2][4];
        #pragma unroll
        for (int nf = 0; nf < 2; nf++)
            #pragma unroll
            for (int q = 0; q < 4; q++) acc[nf][q] = 0.f;

        #pragma unroll 8
        for (int t = 0; t < 16; t++) {    // k = t*16
            uint32_t a[4], bb[4];
            ldsm_x4(a, abase_s + t * 32);
            ldsm_x4(bb, b_base + t * 32);
            mma_bf16(acc[0], a, bb);
            mma_bf16(acc[1], a, bb + 2);
        }

        // stage GEMM result: st[batch 0..15][local col 0..127]
        #pragma unroll
        for (int nf = 0; nf < 2; nf++) {
            int col = w * 16 + nf * 8 + lc * 2;
            *(float2*)&st[lr * 132 + col] = make_float2(acc[nf][0], acc[nf][1]);
            *(float2*)&st[(lr + 8) * 132 + col] = make_float2(acc[nf][2], acc[nf][3]);
        }
        __syncthreads();

        // epilogue: thread handles batch bl, j cols jl2, jl2+1 (gx preloaded)
        float2 v0 = *(const float2*)&st[bl * 132 +       jl2];
        float2 v1 = *(const float2*)&st[bl * 132 +  32 + jl2];
        float2 v2 = *(const float2*)&st[bl * 132 +  64 + jl2];
        float2 v3 = *(const float2*)&st[bl * 132 +  96 + jl2];
        float gi[2] = {v0.x + x0.x, v0.y + x0.y};
        float gf[2] = {v1.x + x1.x, v1.y + x1.y};
        float gg[2] = {v2.x + x2.x, v2.y + x2.y};
        float go[2] = {v3.x + x3.x, v3.y + x3.y};

        float hn[2];
        #pragma unroll
        for (int k = 0; k < 2; k++) {
            float si = sigmoid_fast(gi[k]);
            float sf = sigmoid_fast(gf[k]);
            float so = sigmoid_fast(go[k]);
            float cn = sf * creg[k] + si * tanh_fast(gg[k]);
            creg[k] = cn;
            hn[k] = so * tanh_fast(cn);
        }

        // bf16 h word: reused for DSMEM fan-out and the gmem store
        uint32_t pw = pack_bf16(hn[0], hn[1]);

        // broadcast into all 8 cluster CTAs' next-phase buffer
        uint32_t woff = (uint32_t)(((s + 1) & 1) * (16 * 132)
                      + bl * 132 + jt * 16 + (jl2 >> 1));
        uint32_t baddr = hs_addr + woff * 4;
        #pragma unroll
        for (int r = 0; r < 8; r++) {
            uint32_t ra;
            asm("mapa.shared::cluster.u32 %0, %1, %2;" : "=r"(ra) : "r"(baddr), "r"(r));
            asm volatile("st.shared::cluster.b32 [%0], %1;" :: "r"(ra), "r"(pw) : "memory");
        }

        CLUSTER_ARRIVE();   // release our h writes; peers' WAIT picks them up

        // ---- off-chain work overlapping barrier skew ----
        // bf16 h to gmem for emit (fire-and-forget)
        hbbase[(size_t)(s + 1) * BB * (HH / 2)
               + (size_t)(b0 + bl) * (HH / 2) + jt * 16 + (jl2 >> 1)] = pw;

        // prefetch gx[s+1] into registers (independent of h)
        if (s + 1 < lenmax) {
            const float* gxn = gx_td + (size_t)(s + 1) * BB * GG;
            x0 = *(const float2*)(gxn);
            x1 = *(const float2*)(gxn + 256);
            x2 = *(const float2*)(gxn + 512);
            x3 = *(const float2*)(gxn + 768);
        }
    }
    CLUSTER_WAIT();   // match final arrive
}

// ---------------------------------------------------------------------------
// emit via bf16 MMA (fp32 accumulate). h already bf16 in gmem (raw uint4 copy).
// emit[b][s][t] = b_out[t] + h_f[s].Wout[t][0:256] + h_b[len-1-s].Wout[t][256:512]
// ---------------------------------------------------------------------------
#define EMIT_SMEM (2 * 32 * 260 * 4)

__global__ __launch_bounds__(256) void emit_kernel(
    const float* __restrict__ Wout, const float* __restrict__ bout,
    const int* __restrict__ lens)
{
    extern __shared__ uint32_t es[];
    uint32_t* hbw = es;            // [32 s][260 words] bf16x2
    uint32_t* wbw = es + 32 * 260; // [32 t][260 words] bf16x2

    int b = blockIdx.x;
    int s0 = blockIdx.y * 32;
    int len = lens[b];
    if (s0 >= len) return;

    int tid = threadIdx.x;
    for (int idx = tid; idx < 32 * 64; idx += 256) {
        int sl = idx >> 6;
        int qw = (idx & 63) * 4;     // word offset 0..252
        int s = s0 + sl;
        uint4 v = make_uint4(0u, 0u, 0u, 0u);
        if (s < len) {
            if (qw < 128) v = *(const uint4*)&g_hb[0][s + 1][b][qw];
            else          v = *(const uint4*)&g_hb[1][len - s][b][qw - 128];
        }
        *(uint4*)&hbw[sl * 260 + qw] = v;
    }
    for (int idx = tid; idx < 32 * 128; idx += 256) {
        int t = idx >> 7, q4 = idx & 127;
        float4 wv = *(const float4*)&Wout[t * 512 + q4 * 4];
        wbw[t * 260 + q4 * 2]     = pack_bf16(wv.x, wv.y);
        wbw[t * 260 + q4 * 2 + 1] = pack_bf16(wv.z, wv.w);
    }
    __syncthreads();

    const int lane = tid & 31, w = tid >> 5;
    const int m2 = w >> 2, n4 = w & 3;
    const int lr = lane >> 2, lc = lane & 3;

    float acc[4] = {0.f, 0.f, 0.f, 0.f};
    const int arow = (m2 * 16 + lr) * 260;
    const int brow = (n4 * 8 + lr) * 260;

    #pragma unroll 8
    for (int kc = 0; kc < 256; kc += 8) {
        uint32_t a[4], bb[2];
        a[0] = hbw[arow + kc + lc];
        a[1] = hbw[arow + 8 * 260 + kc + lc];
        a[2] = hbw[arow + kc + 4 + lc];
        a[3] = hbw[arow + 8 * 260 + kc + 4 + lc];
        bb[0] = wbw[brow + kc + lc];
        bb[1] = wbw[brow + kc + 4 + lc];
        mma_bf16(acc, a, bb);
    }

    int t = n4 * 8 + lc * 2;
    float b0v = bout[t], b1v = bout[t + 1];
    int r0 = s0 + m2 * 16 + lr;
    if (r0 < len)
        *(float2*)&g_emit[b][r0][t] = make_float2(acc[0] + b0v, acc[1] + b1v);
    if (r0 + 8 < len)
        *(float2*)&g_emit[b][r0 + 8][t] = make_float2(acc[2] + b0v, acc[3] + b1v);
}

// ---------------------------------------------------------------------------
// Per-batch CRF, one warp per b. E=exp(trans) in registers, 4-way split dot
// chain, max rescale every 8 steps, em prefetched one step ahead (register)
// so its L2 latency is off the recursion chain.
// ---------------------------------------------------------------------------
__global__ void crf_kernel(
    const float* __restrict__ trans,
    const int* __restrict__ tags,
    const int* __restrict__ lens,
    float* __restrict__ out)
{
    int b = blockIdx.x;
    int j = threadIdx.x;   // 0..31
    __shared__ float tr[32][33];

    int len = lens[b];
    for (int idx = j; idx < 1024; idx += 32)
        tr[idx >> 5][idx & 31] = trans[idx];
    __syncwarp();

    float E[32];
    #pragma unroll
    for (int i = 0; i < 32; i++) E[i] = __expf(tr[i][j]);

    const int* tg = tags + b * SS;
    const float* em = &g_emit[b][0][0];

    float rs = 0.f;
    for (int s = j; s < len; s += 32) {
        int t1 = tg[s];
        float v = em[s * 32 + t1];
        if (s > 0) v += tr[tg[s - 1]][t1];
        rs += v;
    }
    #pragma unroll
    for (int o = 16; o; o >>= 1) rs += __shfl_xor_sync(0xffffffffu, rs, o);

    float alpha = em[j];
    float M = alpha;
    #pragma unroll
    for (int o = 16; o; o >>= 1) M = fmaxf(M, __shfl_xor_sync(0xffffffffu, M, o));
    float beta = __expf(alpha - M);
    float em_next = em[32 + j];          // prefetch s=1

    for (int s = 1; s < len; s++) {
        float em_cur = em_next;
        if (s + 1 < len) em_next = em[(s + 1) * 32 + j];   // off-chain prefetch
        float d0 = 0.f, d1 = 0.f, d2 = 0.f, d3 = 0.f;
        #pragma unroll
        for (int i = 0; i < 32; i += 4) {
            d0 = fmaf(__shfl_sync(0xffffffffu, beta, i),     E[i],     d0);
            d1 = fmaf(__shfl_sync(0xffffffffu, beta, i + 1), E[i + 1], d1);
            d2 = fmaf(__shfl_sync(0xffffffffu, beta, i + 2), E[i + 2], d2);
            d3 = fmaf(__shfl_sync(0xffffffffu, beta, i + 3), E[i + 3], d3);
        }
        alpha = M + __logf((d0 + d1) + (d2 + d3)) + em_cur;
        if ((s & 7) == 0) {
            float m2 = alpha;
            #pragma unroll
            for (int o = 16; o; o >>= 1)
                m2 = fmaxf(m2, __shfl_xor_sync(0xffffffffu, m2, o));
            M = m2;
        }
        beta = __expf(alpha - M);
    }

    float m = alpha;
    #pragma unroll
    for (int o = 16; o; o >>= 1) m = fmaxf(m, __shfl_xor_sync(0xffffffffu, m, o));
    float e = __expf(alpha - m);
    #pragma unroll
    for (int o = 16; o; o >>= 1) e += __shfl_xor_sync(0xffffffffu, e, o);
    float logz = m + __logf(e);
    if (j == 0) out[b] = logz - rs;
}

// ---------------------------------------------------------------------------
extern "C" void kernel_launch(void* const* d_in, const int* in_sizes, int n_in,
                              void* d_out, int out_size)
{
    const float* embed = (const float*)d_in[0];
    const float* Wih_f = (const float*)d_in[1];
    const float* Whh_f = (const float*)d_in[2];
    const float* bih_f = (const float*)d_in[3];
    const float* bhh_f = (const float*)d_in[4];
    const float* Wih_b = (const float*)d_in[5];
    const float* Whh_b = (const float*)d_in[6];
    const float* bih_b = (const float*)d_in[7];
    const float* bhh_b = (const float*)d_in[8];
    const float* Wout  = (const float*)d_in[9];
    const float* bout  = (const float*)d_in[10];
    const float* trans = (const float*)d_in[11];
    const int* sent = (const int*)d_in[12];
    const int* tags = (const int*)d_in[13];
    const int* lens = (const int*)d_in[14];
    float* out = (float*)d_out;

    cudaFuncSetAttribute(gemm_inproj_tc,
                         cudaFuncAttributeMaxDynamicSharedMemorySize, INP_SMEM);
    cudaFuncSetAttribute(lstm_persist,
                         cudaFuncAttributeMaxDynamicSharedMemorySize, LSTM_SMEM);
    cudaFuncSetAttribute(emit_kernel,
                         cudaFuncAttributeMaxDynamicSharedMemorySize, EMIT_SMEM);

    dim3 g1(2048, 8, 2);
    gemm_inproj_tc<<<g1, 256, INP_SMEM>>>(embed, Wih_f, Wih_b,
                                          bih_f, bhh_f, bih_b, bhh_b, sent, lens);

    dim3 gl(8, 32);
    lstm_persist<<<gl, 256, LSTM_SMEM>>>(Whh_f, Whh_b, lens);

    dim3 ge(256, 16);
    emit_kernel<<<ge, 256, EMIT_SMEM>>>(Wout, bout, lens);

    crf_kernel<<<256, 32>>>(trans, tags, lens, out);
}

// round 17
// speedup vs baseline: 1.2905x; 1.1245x over previous
#include <cuda_runtime.h>
#include <cuda_bf16.h>
#include <math.h>
#include <stdint.h>

#define SS 512
#define BB 256
#define EE 256
#define HH 256
#define GG 1024   // 4*H
#define TT 32

// Scratch (device globals: allocation-free contract)
__device__ float g_gx[2][SS][BB][GG];            // pre-activations
__device__ uint32_t g_hb[2][SS + 1][BB][HH / 2]; // bf16x2 hidden states (for emit)
__device__ float g_emit[BB][SS][TT];             // emission scores

// ---------------------------------------------------------------------------
__device__ __forceinline__ void mma_bf16(float d[4], const uint32_t a[4], const uint32_t b[2]) {
    asm volatile(
        "mma.sync.aligned.m16n8k16.row.col.f32.bf16.bf16.f32 "
        "{%0,%1,%2,%3}, {%4,%5,%6,%7}, {%8,%9}, {%0,%1,%2,%3};\n"
        : "+f"(d[0]), "+f"(d[1]), "+f"(d[2]), "+f"(d[3])
        : "r"(a[0]), "r"(a[1]), "r"(a[2]), "r"(a[3]), "r"(b[0]), "r"(b[1]));
}

__device__ __forceinline__ void ldsm_x4(uint32_t r[4], uint32_t addr) {
    asm volatile("ldmatrix.sync.aligned.m8n8.x4.shared.b16 {%0,%1,%2,%3}, [%4];"
        : "=r"(r[0]), "=r"(r[1]), "=r"(r[2]), "=r"(r[3]) : "r"(addr));
}

__device__ __forceinline__ uint32_t pack_bf16(float lo, float hi) {
    __nv_bfloat162 t = __floats2bfloat162_rn(lo, hi);
    return *(uint32_t*)&t;
}

__device__ __forceinline__ uint32_t smem_u32(const void* p) {
    uint32_t a;
    asm("{ .reg .u64 t; cvta.to.shared.u64 t, %1; cvt.u32.u64 %0, t; }"
        : "=r"(a) : "l"(p));
    return a;
}

__device__ __forceinline__ float tanh_fast(float x) {
    float y;
    asm("tanh.approx.f32 %0, %1;" : "=f"(y) : "f"(x));
    return y;
}
__device__ __forceinline__ float sigmoid_fast(float x) {
    return fmaf(tanh_fast(0.5f * x), 0.5f, 0.5f);
}

#define CLUSTER_SYNC() do { \
    asm volatile("barrier.cluster.arrive.aligned;" ::: "memory"); \
    asm volatile("barrier.cluster.wait.aligned;" ::: "memory"); \
} while (0)

#define MBARRIER_INIT(mbar, count) \
    asm volatile("mbarrier.init.shared.b64 [%0], %1;" \
        :: "r"((uint32_t)(mbar)), "r"((uint32_t)(count)) : "memory")
#define MBARRIER_EXPECT_TX(mbar, tx) \
    asm volatile("mbarrier.arrive.expect_tx.shared.b64 _, [%0], %1;" \
        :: "r"((uint32_t)(mbar)), "r"((uint32_t)(tx)) : "memory")
// parity wait with CLUSTER-scope acquire (remote st.async data)
#define MBARRIER_WAIT_PARITY_CL(mbar, parity) do { \
    asm volatile( \
        "{\n\t.reg .pred P1;\n\t" \
        "WAIT_LOOP_%=:\n\t" \
        "mbarrier.try_wait.parity.acquire.cluster.shared::cta.b64 P1, [%0], %1, 0x989680;\n\t" \
        "@P1 bra.uni WAIT_DONE_%=;\n\t" \
        "bra.uni WAIT_LOOP_%=;\n\t" \
        "WAIT_DONE_%=:\n\t}" \
        :: "r"((uint32_t)(mbar)), "r"((uint32_t)(parity)) : "memory"); \
} while (0)
// remote smem store with mbarrier tx completion (data + signal in one op)
#define ST_ASYNC_B32(addr, val, mbar) \
    asm volatile("st.async.weak.shared::cluster.mbarrier::complete_tx::bytes.b32 [%0], %1, [%2];" \
        :: "r"((uint32_t)(addr)), "r"(val), "r"((uint32_t)(mbar)) : "memory")

// ---------------------------------------------------------------------------
// Input projection with fused embedding gather (bf16 MMA + ldmatrix). R8-exact.
// ---------------------------------------------------------------------------
#define INP_SMEM ((64 + 128) * 132 * 4)

__global__ __launch_bounds__(256) void gemm_inproj_tc(
    const float* __restrict__ embed,
    const float* __restrict__ Wf, const float* __restrict__ Wb,
    const float* __restrict__ bih_f, const float* __restrict__ bhh_f,
    const float* __restrict__ bih_b, const float* __restrict__ bhh_b,
    const int* __restrict__ sent, const int* __restrict__ lens)
{
    extern __shared__ uint32_t smw[];
    uint32_t* au = smw;              // A: 64 rows x 132 words (bf16x2)
    uint32_t* wu = smw + 64 * 132;   // W: 128 cols x 132 words
    __shared__ int rowid[64];

    const int dir = blockIdx.z;
    const int m0 = blockIdx.x * 64;
    const int n0 = blockIdx.y * 128;
    const int s  = m0 >> 8;
    const int bf = m0 & 255;
    if (s >= lens[bf]) return;   // lengths sorted desc

    const int tid = threadIdx.x;
    if (tid < 64) {
        int b = bf + tid;
        int len = lens[b];
        int ss = (dir == 1 && s < len) ? (len - 1 - s) : s;
        rowid[tid] = sent[b * SS + ss];
    }
    __syncthreads();

    for (int idx = tid; idx < 64 * 64; idx += 256) {
        int r = idx >> 6, q4 = idx & 63;
        float4 v = *(const float4*)(embed + (size_t)rowid[r] * EE + q4 * 4);
        au[r * 132 + q4 * 2]     = pack_bf16(v.x, v.y);
        au[r * 132 + q4 * 2 + 1] = pack_bf16(v.z, v.w);
    }
    const float* __restrict__ W = dir ? Wb : Wf;
    for (int idx = tid; idx < 128 * 64; idx += 256) {
        int c = idx >> 6, q4 = idx & 63;
        float4 w = *(const float4*)(W + (size_t)(n0 + c) * EE + q4 * 4);
        wu[c * 132 + q4 * 2]     = pack_bf16(w.x, w.y);
        wu[c * 132 + q4 * 2 + 1] = pack_bf16(w.z, w.w);
    }
    __syncthreads();

    const int lane = tid & 31, wid = tid >> 5;
    const int wm = wid & 3, wn = wid >> 2;
    const int lr = lane >> 2, lc = lane & 3;

    float acc[8][4];
    #pragma unroll
    for (int i = 0; i < 8; i++)
        #pragma unroll
        for (int j = 0; j < 4; j++) acc[i][j] = 0.f;

    const uint32_t au_addr = smem_u32(au);
    const uint32_t wu_addr = smem_u32(wu);
    const uint32_t a_base = au_addr +
        (((wm * 16 + (lane & 15)) * 132 + ((lane >> 4) << 2)) << 2);
    const uint32_t b_base = wu_addr +
        ((((wn * 64) + (lane & 7) + ((lane >> 4) << 3)) * 132 + (((lane >> 3) & 1) << 2)) << 2);

    #pragma unroll 4
    for (int t = 0; t < 16; t++) {        // k = t*16
        uint32_t a[4];
        ldsm_x4(a, a_base + t * 32);
        #pragma unroll
        for (int p = 0; p < 4; p++) {
            uint32_t bb[4];
            ldsm_x4(bb, b_base + p * (16 * 132 * 4) + t * 32);
            mma_bf16(acc[p * 2],     a, bb);
            mma_bf16(acc[p * 2 + 1], a, bb + 2);
        }
    }

    const float* bi = dir ? bih_b : bih_f;
    const float* bh = dir ? bhh_b : bhh_f;
    float* gxp = &g_gx[dir][0][0][0];
    const int row = m0 + wm * 16 + lr;
    #pragma unroll
    for (int nf = 0; nf < 8; nf++) {
        int n = n0 + wn * 64 + nf * 8 + lc * 2;
        float b0v = bi[n] + bh[n];
        float b1v = bi[n + 1] + bh[n + 1];
        *(float2*)(gxp + (size_t)row * GG + n) =
            make_float2(acc[nf][0] + b0v, acc[nf][1] + b1v);
        *(float2*)(gxp + (size_t)(row + 8) * GG + n) =
            make_float2(acc[nf][2] + b0v, acc[nf][3] + b1v);
    }
}

// ---------------------------------------------------------------------------
// Persistent bidirectional LSTM: clusters of 8 CTAs per (dir, 16-batch tile),
// 256 CTAs -> 2 clusters/SM. Step synchronization = double-buffered mbarrier
// full/empty pipeline: h fan-out via st.async (data + tx-signal to each
// peer's phase mbarrier, 8192 B expected per phase), consumer does parity
// try_wait.acquire.cluster (~90 cyc vs ~490 for barrier.cluster) and proceeds
// as soon as ITS inputs arrive (tolerates 1 step of producer skew).
// Buffer-overwrite safety: a producer reaches step s+1 stores (which target
// buf[s&1]) only after its s+1 wait, which needs the owner's step-s stores —
// and those data-depend on the owner's step-s reads of buf[s&1].
// ---------------------------------------------------------------------------
#define LSTM_ST_WORDS (16 * 132)           // fp32 staging [16][132]
#define LSTM_WS_WORDS (128 * 132)          // bf16x2 weights [128 cols][132]
#define LSTM_HS_WORDS (2 * 16 * 132)       // bf16x2 h, double-buffered
#define LSTM_SMEM ((LSTM_ST_WORDS + LSTM_WS_WORDS + LSTM_HS_WORDS) * 4)
#define LSTM_TX_BYTES 8192                 // 8 CTAs x 256 thr x 4 B per phase

__global__ __launch_bounds__(256, 2) __cluster_dims__(8, 1, 1)
void lstm_persist(
    const float* __restrict__ Whh_f, const float* __restrict__ Whh_b,
    const int* __restrict__ lens)
{
    extern __shared__ float smf[];
    float* st = smf;                                    // [16][132] fp32
    uint32_t* wsu = (uint32_t*)(smf + LSTM_ST_WORDS);   // [128][132] bf16x2
    uint32_t* hsu = wsu + LSTM_WS_WORDS;                // [2][16][132] bf16x2
    __shared__ __align__(8) unsigned long long mbar_s[2];

    const int tid = threadIdx.x;
    const int jt  = blockIdx.x;          // cluster rank 0..7 -> j-cols jt*32..
    const int dir = blockIdx.y >> 4;
    const int mb  = blockIdx.y & 15;
    const int b0  = mb * 16;
    const int lenmax = lens[b0];         // same for whole cluster

    // Load bf16 weights. Local col c (0..127): gate g=c>>5, j=jt*32+(c&31)
    const float* __restrict__ W = dir ? Whh_b : Whh_f;
    for (int idx = tid; idx < 128 * 64; idx += 256) {
        int c = idx >> 6, q4 = idx & 63;
        int n = ((c >> 5) << 8) + jt * 32 + (c & 31);
        float4 w = *(const float4*)(W + (size_t)n * HH + q4 * 4);
        wsu[c * 132 + q4 * 2]     = pack_bf16(w.x, w.y);
        wsu[c * 132 + q4 * 2 + 1] = pack_bf16(w.z, w.w);
    }
    for (int idx = tid; idx < LSTM_HS_WORDS; idx += 256) hsu[idx] = 0u;

    const uint32_t mbr = smem_u32(mbar_s);
    if (tid == 0) {
        MBARRIER_INIT(mbr, 1);        // mbar[0]: steps 2,4,6,...
        MBARRIER_INIT(mbr + 8, 1);    // mbar[1]: steps 1,3,5,...
    }

    const int lane = tid & 31, w = tid >> 5;
    const int lr = lane >> 2, lc = lane & 3;
    const int bl  = tid >> 4;            // epilogue batch row 0..15
    const int jl2 = (tid & 15) * 2;      // epilogue j pair

    float creg[2] = {0.f, 0.f};

    const float* gxbase = &g_gx[dir][0][0][0];
    uint32_t* hbbase = &g_hb[dir][0][0][0];
    const uint32_t hs_addr = smem_u32(hsu);
    const uint32_t ws_addr = smem_u32(wsu);
    const uint32_t a_base = hs_addr +
        ((((lane & 15)) * 132 + ((lane >> 4) << 2)) << 2);
    const uint32_t b_base = ws_addr +
        ((((w * 16) + (lane & 7) + ((lane >> 4) << 3)) * 132 + (((lane >> 3) & 1) << 2)) << 2);

    const float* gx_td = gxbase + (size_t)(b0 + bl) * GG + jt * 32 + jl2;

    __syncthreads();     // weights + zeroed h + mbarriers ready locally
    // peers' mbarrier init + zeroed buffers must precede any st.async
    CLUSTER_SYNC();

    // pre-post expected tx for the first use of each mbarrier
    if (tid == 0) {
        MBARRIER_EXPECT_TX(mbr + 8, LSTM_TX_BYTES);  // step-1 data
        MBARRIER_EXPECT_TX(mbr,     LSTM_TX_BYTES);  // step-2 data
    }

    uint32_t par0 = 0, par1 = 0;

    // prefetch gx[0] into registers
    float2 x0 = *(const float2*)(gx_td);
    float2 x1 = *(const float2*)(gx_td + 256);
    float2 x2 = *(const float2*)(gx_td + 512);
    float2 x3 = *(const float2*)(gx_td + 768);

    for (int s = 0; s < lenmax; s++) {
        // ---- wait for this step's h inputs (step 0 uses zeroed buf0) ----
        if (s > 0) {
            if (s & 1) {
                MBARRIER_WAIT_PARITY_CL(mbr + 8, par1);
                par1 ^= 1;
                if (tid == 0) MBARRIER_EXPECT_TX(mbr + 8, LSTM_TX_BYTES); // for s+2
            } else {
                MBARRIER_WAIT_PARITY_CL(mbr, par0);
                par0 ^= 1;
                if (tid == 0) MBARRIER_EXPECT_TX(mbr, LSTM_TX_BYTES);     // for s+2
            }
        }

        const uint32_t abase_s = a_base + (uint32_t)((s & 1) * (16 * 132 * 4));

        float acc[2][4];
        #pragma unroll
        for (int nf = 0; nf < 2; nf++)
            #pragma unroll
            for (int q = 0; q < 4; q++) acc[nf][q] = 0.f;

        #pragma unroll 8
        for (int t = 0; t < 16; t++) {    // k = t*16
            uint32_t a[4], bb[4];
            ldsm_x4(a, abase_s + t * 32);
            ldsm_x4(bb, b_base + t * 32);
            mma_bf16(acc[0], a, bb);
            mma_bf16(acc[1], a, bb + 2);
        }

        // stage GEMM result: st[batch 0..15][local col 0..127]
        #pragma unroll
        for (int nf = 0; nf < 2; nf++) {
            int col = w * 16 + nf * 8 + lc * 2;
            *(float2*)&st[lr * 132 + col] = make_float2(acc[nf][0], acc[nf][1]);
            *(float2*)&st[(lr + 8) * 132 + col] = make_float2(acc[nf][2], acc[nf][3]);
        }
        __syncthreads();

        // epilogue: thread handles batch bl, j cols jl2, jl2+1 (gx preloaded)
        float2 v0 = *(const float2*)&st[bl * 132 +       jl2];
        float2 v1 = *(const float2*)&st[bl * 132 +  32 + jl2];
        float2 v2 = *(const float2*)&st[bl * 132 +  64 + jl2];
        float2 v3 = *(const float2*)&st[bl * 132 +  96 + jl2];
        float gi[2] = {v0.x + x0.x, v0.y + x0.y};
        float gf[2] = {v1.x + x1.x, v1.y + x1.y};
        float gg[2] = {v2.x + x2.x, v2.y + x2.y};
        float go[2] = {v3.x + x3.x, v3.y + x3.y};

        float hn[2];
        #pragma unroll
        for (int k = 0; k < 2; k++) {
            float si = sigmoid_fast(gi[k]);
            float sf = sigmoid_fast(gf[k]);
            float so = sigmoid_fast(go[k]);
            float cn = sf * creg[k] + si * tanh_fast(gg[k]);
            creg[k] = cn;
            hn[k] = so * tanh_fast(cn);
        }

        // bf16 h word: reused for fan-out and the gmem store
        uint32_t pw = pack_bf16(hn[0], hn[1]);

        // fan-out to all 8 cluster CTAs' next-phase buffer via st.async,
        // signaling each peer's phase mbarrier (skip useless final-step send)
        if (s + 1 < lenmax) {
            uint32_t woff = (uint32_t)(((s + 1) & 1) * (16 * 132)
                          + bl * 132 + jt * 16 + (jl2 >> 1));
            uint32_t baddr = hs_addr + woff * 4;
            uint32_t mtar = mbr + 8u * (uint32_t)((s + 1) & 1);
            #pragma unroll
            for (int r = 0; r < 8; r++) {
                uint32_t ra, rm;
                asm("mapa.shared::cluster.u32 %0, %1, %2;" : "=r"(ra) : "r"(baddr), "r"(r));
                asm("mapa.shared::cluster.u32 %0, %1, %2;" : "=r"(rm) : "r"(mtar), "r"(r));
                ST_ASYNC_B32(ra, pw, rm);
            }
        }

        // ---- off-chain work ----
        // bf16 h to gmem for emit (fire-and-forget)
        hbbase[(size_t)(s + 1) * BB * (HH / 2)
               + (size_t)(b0 + bl) * (HH / 2) + jt * 16 + (jl2 >> 1)] = pw;

        // prefetch gx[s+1] into registers (independent of h)
        if (s + 1 < lenmax) {
            const float* gxn = gx_td + (size_t)(s + 1) * BB * GG;
            x0 = *(const float2*)(gxn);
            x1 = *(const float2*)(gxn + 256);
            x2 = *(const float2*)(gxn + 512);
            x3 = *(const float2*)(gxn + 768);
        }
    }

    // all consumed tx landed before our last wait; sync before teardown
    CLUSTER_SYNC();
}

// ---------------------------------------------------------------------------
// emit via bf16 MMA (fp32 accumulate). h already bf16 in gmem (raw uint4 copy).
// ---------------------------------------------------------------------------
#define EMIT_SMEM (2 * 32 * 260 * 4)

__global__ __launch_bounds__(256) void emit_kernel(
    const float* __restrict__ Wout, const float* __restrict__ bout,
    const int* __restrict__ lens)
{
    extern __shared__ uint32_t es[];
    uint32_t* hbw = es;            // [32 s][260 words] bf16x2
    uint32_t* wbw = es + 32 * 260; // [32 t][260 words] bf16x2

    int b = blockIdx.x;
    int s0 = blockIdx.y * 32;
    int len = lens[b];
    if (s0 >= len) return;

    int tid = threadIdx.x;
    for (int idx = tid; idx < 32 * 64; idx += 256) {
        int sl = idx >> 6;
        int qw = (idx & 63) * 4;     // word offset 0..252
        int s = s0 + sl;
        uint4 v = make_uint4(0u, 0u, 0u, 0u);
        if (s < len) {
            if (qw < 128) v = *(const uint4*)&g_hb[0][s + 1][b][qw];
            else          v = *(const uint4*)&g_hb[1][len - s][b][qw - 128];
        }
        *(uint4*)&hbw[sl * 260 + qw] = v;
    }
    for (int idx = tid; idx < 32 * 128; idx += 256) {
        int t = idx >> 7, q4 = idx & 127;
        float4 wv = *(const float4*)&Wout[t * 512 + q4 * 4];
        wbw[t * 260 + q4 * 2]     = pack_bf16(wv.x, wv.y);
        wbw[t * 260 + q4 * 2 + 1] = pack_bf16(wv.z, wv.w);
    }
    __syncthreads();

    const int lane = tid & 31, w = tid >> 5;
    const int m2 = w >> 2, n4 = w & 3;
    const int lr = lane >> 2, lc = lane & 3;

    float acc[4] = {0.f, 0.f, 0.f, 0.f};
    const int arow = (m2 * 16 + lr) * 260;
    const int brow = (n4 * 8 + lr) * 260;

    #pragma unroll 8
    for (int kc = 0; kc < 256; kc += 8) {
        uint32_t a[4], bb[2];
        a[0] = hbw[arow + kc + lc];
        a[1] = hbw[arow + 8 * 260 + kc + lc];
        a[2] = hbw[arow + kc + 4 + lc];
        a[3] = hbw[arow + 8 * 260 + kc + 4 + lc];
        bb[0] = wbw[brow + kc + lc];
        bb[1] = wbw[brow + kc + 4 + lc];
        mma_bf16(acc, a, bb);
    }

    int t = n4 * 8 + lc * 2;
    float b0v = bout[t], b1v = bout[t + 1];
    int r0 = s0 + m2 * 16 + lr;
    if (r0 < len)
        *(float2*)&g_emit[b][r0][t] = make_float2(acc[0] + b0v, acc[1] + b1v);
    if (r0 + 8 < len)
        *(float2*)&g_emit[b][r0 + 8][t] = make_float2(acc[2] + b0v, acc[3] + b1v);
}

// ---------------------------------------------------------------------------
// Per-batch CRF, one warp per b (R15-exact: no em prefetch, rescale every 8).
// ---------------------------------------------------------------------------
__global__ void crf_kernel(
    const float* __restrict__ trans,
    const int* __restrict__ tags,
    const int* __restrict__ lens,
    float* __restrict__ out)
{
    int b = blockIdx.x;
    int j = threadIdx.x;   // 0..31
    __shared__ float tr[32][33];

    int len = lens[b];
    for (int idx = j; idx < 1024; idx += 32)
        tr[idx >> 5][idx & 31] = trans[idx];
    __syncwarp();

    float E[32];
    #pragma unroll
    for (int i = 0; i < 32; i++) E[i] = __expf(tr[i][j]);

    const int* tg = tags + b * SS;
    const float* em = &g_emit[b][0][0];

    float rs = 0.f;
    for (int s = j; s < len; s += 32) {
        int t1 = tg[s];
        float v = em[s * 32 + t1];
        if (s > 0) v += tr[tg[s - 1]][t1];
        rs += v;
    }
    #pragma unroll
    for (int o = 16; o; o >>= 1) rs += __shfl_xor_sync(0xffffffffu, rs, o);

    float alpha = em[j];
    float M = alpha;
    #pragma unroll
    for (int o = 16; o; o >>= 1) M = fmaxf(M, __shfl_xor_sync(0xffffffffu, M, o));
    float beta = __expf(alpha - M);

    for (int s = 1; s < len; s++) {
        float d0 = 0.f, d1 = 0.f, d2 = 0.f, d3 = 0.f;
        #pragma unroll
        for (int i = 0; i < 32; i += 4) {
            d0 = fmaf(__shfl_sync(0xffffffffu, beta, i),     E[i],     d0);
            d1 = fmaf(__shfl_sync(0xffffffffu, beta, i + 1), E[i + 1], d1);
            d2 = fmaf(__shfl_sync(0xffffffffu, beta, i + 2), E[i + 2], d2);
            d3 = fmaf(__shfl_sync(0xffffffffu, beta, i + 3), E[i + 3], d3);
        }
        alpha = M + __logf((d0 + d1) + (d2 + d3)) + em[s * 32 + j];
        if ((s & 7) == 0) {
            float m2 = alpha;
            #pragma unroll
            for (int o = 16; o; o >>= 1)
                m2 = fmaxf(m2, __shfl_xor_sync(0xffffffffu, m2, o));
            M = m2;
        }
        beta = __expf(alpha - M);
    }

    float m = alpha;
    #pragma unroll
    for (int o = 16; o; o >>= 1) m = fmaxf(m, __shfl_xor_sync(0xffffffffu, m, o));
    float e = __expf(alpha - m);
    #pragma unroll
    for (int o = 16; o; o >>= 1) e += __shfl_xor_sync(0xffffffffu, e, o);
    float logz = m + __logf(e);
    if (j == 0) out[b] = logz - rs;
}

// ---------------------------------------------------------------------------
extern "C" void kernel_launch(void* const* d_in, const int* in_sizes, int n_in,
                              void* d_out, int out_size)
{
    const float* embed = (const float*)d_in[0];
    const float* Wih_f = (const float*)d_in[1];
    const float* Whh_f = (const float*)d_in[2];
    const float* bih_f = (const float*)d_in[3];
    const float* bhh_f = (const float*)d_in[4];
    const float* Wih_b = (const float*)d_in[5];
    const float* Whh_b = (const float*)d_in[6];
    const float* bih_b = (const float*)d_in[7];
    const float* bhh_b = (const float*)d_in[8];
    const float* Wout  = (const float*)d_in[9];
    const float* bout  = (const float*)d_in[10];
    const float* trans = (const float*)d_in[11];
    const int* sent = (const int*)d_in[12];
    const int* tags = (const int*)d_in[13];
    const int* lens = (const int*)d_in[14];
    float* out = (float*)d_out;

    cudaFuncSetAttribute(gemm_inproj_tc,
                         cudaFuncAttributeMaxDynamicSharedMemorySize, INP_SMEM);
    cudaFuncSetAttribute(lstm_persist,
                         cudaFuncAttributeMaxDynamicSharedMemorySize, LSTM_SMEM);
    cudaFuncSetAttribute(emit_kernel,
                         cudaFuncAttributeMaxDynamicSharedMemorySize, EMIT_SMEM);

    dim3 g1(2048, 8, 2);
    gemm_inproj_tc<<<g1, 256, INP_SMEM>>>(embed, Wih_f, Wih_b,
                                          bih_f, bhh_f, bih_b, bhh_b, sent, lens);

    dim3 gl(8, 32);
    lstm_persist<<<gl, 256, LSTM_SMEM>>>(Whh_f, Whh_b, lens);

    dim3 ge(256, 16);
    emit_kernel<<<ge, 256, EMIT_SMEM>>>(Wout, bout, lens);

    crf_kernel<<<256, 32>>>(trans, tags, lens, out);
}